// round 5
// baseline (speedup 1.0000x reference)
#include <cuda_runtime.h>

// ---------------------------------------------------------------------------
// WindowMCA (Swin window attention, B=4096 windows, N=49 tokens, C=256, H=8,
// D=32). Fully fused: one CTA per window does QKV projection, per-head
// attention with relative-position bias + window mask, softmax, PV, and the
// output projection. fp32 throughout (rel-err budget 1e-3; tf32/tcgen05 is
// the planned next step).
// ---------------------------------------------------------------------------

#define NTOK     49
#define CDIM     256
#define HDS      8
#define HDIM     32
#define NTHREADS 512
#define KT       16          // k-tile for weight staging
#define LDN      51          // leading dim of smem q/k/v [C][LDN] (odd -> conflict-free)
#define LDSC     53          // leading dim of smem scores [N][LDSC]
#define SCALE    0.17677669529663687f   // 32^-0.5

// smem layout (floats):
//   sIn : [0, 12544)            staging X, later attention output [n][256]
//   sQ  : [12544, 25600)        [c][LDN]
//   sK  : [25600, 38656)
//   sV  : [38656, 51712)
//   sW  : [51712, 55808)        weight k-tile [KT][256]; reused as scores sS
#define SMEM_FLOATS 55808
#define SMEM_BYTES  (SMEM_FLOATS * 4)

// -------------------------- scratch (device globals) -----------------------
__device__ float g_wqT[CDIM * CDIM];   // W^T with SCALE folded in
__device__ float g_wkT[CDIM * CDIM];
__device__ float g_wvT[CDIM * CDIM];
__device__ float g_woT[CDIM * CDIM];
__device__ float g_bias[HDS * NTOK * NTOK];  // dense rel-pos bias [h][n][m]

// -------------------------- prep kernels -----------------------------------
__global__ void prep_weights(const float* __restrict__ qw, const float* __restrict__ kw,
                             const float* __restrict__ vw, const float* __restrict__ ow) {
    int idx = blockIdx.x * blockDim.x + threadIdx.x;
    if (idx >= CDIM * CDIM) return;
    int o = idx >> 8;          // output channel (row of W)
    int c = idx & 255;         // input channel (contiguous -> coalesced read)
    g_wqT[c * CDIM + o] = qw[idx] * SCALE;   // fold softmax scale into Wq
    g_wkT[c * CDIM + o] = kw[idx];
    g_wvT[c * CDIM + o] = vw[idx];
    g_woT[c * CDIM + o] = ow[idx];
}

__global__ void prep_bias(const float* __restrict__ rpb, const int* __restrict__ relidx) {
    int idx = blockIdx.x * blockDim.x + threadIdx.x;
    if (idx >= HDS * NTOK * NTOK) return;
    int h = idx / (NTOK * NTOK);
    int r = idx % (NTOK * NTOK);
    g_bias[idx] = rpb[relidx[r] * HDS + h];
}

// -------------------------- projection helper ------------------------------
// Computes dst[c][n] = sum_k sIn[n][k] * Wt[k][c] + bias[c]*bscale
// Thread layout: wid = warp (0..15) -> rows n = wid + i*16 (i<4, guarded),
//                lane -> cols c = lane + j*32 (j<8).
__device__ __forceinline__ void project_to_smem(
    const float* __restrict__ Wt, const float* __restrict__ bias, float bscale,
    const float* __restrict__ sIn, float* __restrict__ sW, float* __restrict__ dst,
    int tid, int lane, int wid)
{
    float acc[4][8];
#pragma unroll
    for (int i = 0; i < 4; i++)
#pragma unroll
        for (int j = 0; j < 8; j++) acc[i][j] = 0.f;

    const float4* W4 = (const float4*)Wt;
    float4* sW4 = (float4*)sW;

    for (int k0 = 0; k0 < CDIM; k0 += KT) {
        // stage W tile [KT][256] (rows contiguous in global)
#pragma unroll
        for (int t = 0; t < (KT * CDIM / 4) / NTHREADS; t++)
            sW4[tid + t * NTHREADS] = W4[k0 * (CDIM / 4) + tid + t * NTHREADS];
        __syncthreads();
#pragma unroll
        for (int kk = 0; kk < KT; kk++) {
            float bvv[8];
#pragma unroll
            for (int j = 0; j < 8; j++) bvv[j] = sW[kk * CDIM + lane + j * 32];
#pragma unroll
            for (int i = 0; i < 4; i++) {
                if (i < 3 || wid == 0) {            // row r = wid + i*16 < 49
                    float a = sIn[(wid + i * 16) * CDIM + k0 + kk];
#pragma unroll
                    for (int j = 0; j < 8; j++) acc[i][j] += a * bvv[j];
                }
            }
        }
        __syncthreads();
    }

#pragma unroll
    for (int i = 0; i < 4; i++) {
        if (i < 3 || wid == 0) {
            int r = wid + i * 16;
#pragma unroll
            for (int j = 0; j < 8; j++) {
                int c = lane + j * 32;
                dst[c * LDN + r] = acc[i][j] + bias[c] * bscale;
            }
        }
    }
    __syncthreads();
}

// -------------------------- main fused kernel ------------------------------
__global__ void __launch_bounds__(NTHREADS, 1)
window_attn_kernel(const float* __restrict__ query, const float* __restrict__ key,
                   const float* __restrict__ value, const float* __restrict__ mask,
                   const float* __restrict__ qb, const float* __restrict__ kb,
                   const float* __restrict__ vb, const float* __restrict__ ob,
                   float* __restrict__ out, int nW)
{
    extern __shared__ float smem[];
    float* sIn = smem;
    float* sQ  = smem + 12544;
    float* sK  = smem + 25600;
    float* sV  = smem + 38656;
    float* sW  = smem + 51712;
    float* sS  = sW;                     // reuse weight tile as score buffer

    const int tid  = threadIdx.x;
    const int lane = tid & 31;
    const int wid  = tid >> 5;
    const int b    = blockIdx.x;
    const long base = (long)b * (NTOK * CDIM);

    float4* sIn4 = (float4*)sIn;

    // ---- Q projection ----
    {
        const float4* X4 = (const float4*)(query + base);
        for (int i = tid; i < NTOK * CDIM / 4; i += NTHREADS) sIn4[i] = X4[i];
        __syncthreads();
        project_to_smem(g_wqT, qb, SCALE, sIn, sW, sQ, tid, lane, wid);
    }
    // ---- K projection ----
    {
        const float4* X4 = (const float4*)(key + base);
        for (int i = tid; i < NTOK * CDIM / 4; i += NTHREADS) sIn4[i] = X4[i];
        __syncthreads();
        project_to_smem(g_wkT, kb, 1.f, sIn, sW, sK, tid, lane, wid);
    }
    // ---- V projection ----
    {
        const float4* X4 = (const float4*)(value + base);
        for (int i = tid; i < NTOK * CDIM / 4; i += NTHREADS) sIn4[i] = X4[i];
        __syncthreads();
        project_to_smem(g_wvT, vb, 1.f, sIn, sW, sV, tid, lane, wid);
    }
    // sIn is now free; reused below as attention output [n][256].

    const int w = b % nW;
    const float* maskW = mask + (long)w * NTOK * NTOK;
    const int m0 = lane;
    const int m1 = lane + 32;
    const bool has_m1 = (m1 < NTOK);

    for (int h = 0; h < HDS; h++) {
        const int cb = h * HDIM;

        // ---- scores S[n][m] = sum_d q[n][cb+d] * k[m][cb+d] ----
        float sacc[4][2];
#pragma unroll
        for (int i = 0; i < 4; i++) { sacc[i][0] = 0.f; sacc[i][1] = 0.f; }
#pragma unroll
        for (int d = 0; d < HDIM; d++) {
            const float* kq = sK + (cb + d) * LDN;
            const float* qq = sQ + (cb + d) * LDN;
            float k0v = kq[m0];
            float k1v = has_m1 ? kq[m1] : 0.f;
#pragma unroll
            for (int i = 0; i < 4; i++) {
                if (i < 3 || wid == 0) {
                    float a = qq[wid + i * 16];
                    sacc[i][0] += a * k0v;
                    sacc[i][1] += a * k1v;
                }
            }
        }
        const float* biasH = g_bias + h * NTOK * NTOK;
#pragma unroll
        for (int i = 0; i < 4; i++) {
            if (i < 3 || wid == 0) {
                int n = wid + i * 16;
                sS[n * LDSC + m0] = sacc[i][0] + biasH[n * NTOK + m0] + maskW[n * NTOK + m0];
                if (has_m1)
                    sS[n * LDSC + m1] = sacc[i][1] + biasH[n * NTOK + m1] + maskW[n * NTOK + m1];
            }
        }
        __syncthreads();

        // ---- softmax over rows ----
        if (tid < NTOK) {
            float* row = sS + tid * LDSC;
            float mx = -1e30f;
            for (int m = 0; m < NTOK; m++) mx = fmaxf(mx, row[m]);
            float sum = 0.f;
            for (int m = 0; m < NTOK; m++) { float e = __expf(row[m] - mx); row[m] = e; sum += e; }
            float inv = 1.f / sum;
            for (int m = 0; m < NTOK; m++) row[m] *= inv;
        }
        __syncthreads();

        // ---- O[n][d] = sum_m P[n][m] * v[m][cb+d]  (d = lane) ----
        float oacc[4] = {0.f, 0.f, 0.f, 0.f};
        const float* vcol = sV + (cb + lane) * LDN;
        for (int m = 0; m < NTOK; m++) {
            float vv = vcol[m];
#pragma unroll
            for (int i = 0; i < 4; i++) {
                if (i < 3 || wid == 0)
                    oacc[i] += sS[(wid + i * 16) * LDSC + m] * vv;
            }
        }
#pragma unroll
        for (int i = 0; i < 4; i++) {
            if (i < 3 || wid == 0)
                sIn[(wid + i * 16) * CDIM + cb + lane] = oacc[i];
        }
        __syncthreads();
    }

    // ---- output projection: out[n][c] = sum_k sIn[n][k] * Wo^T[k][c] + ob[c]
    {
        float acc[4][8];
#pragma unroll
        for (int i = 0; i < 4; i++)
#pragma unroll
            for (int j = 0; j < 8; j++) acc[i][j] = 0.f;

        const float4* W4 = (const float4*)g_woT;
        float4* sW4 = (float4*)sW;
        for (int k0 = 0; k0 < CDIM; k0 += KT) {
#pragma unroll
            for (int t = 0; t < (KT * CDIM / 4) / NTHREADS; t++)
                sW4[tid + t * NTHREADS] = W4[k0 * (CDIM / 4) + tid + t * NTHREADS];
            __syncthreads();
#pragma unroll
            for (int kk = 0; kk < KT; kk++) {
                float bvv[8];
#pragma unroll
                for (int j = 0; j < 8; j++) bvv[j] = sW[kk * CDIM + lane + j * 32];
#pragma unroll
                for (int i = 0; i < 4; i++) {
                    if (i < 3 || wid == 0) {
                        float a = sIn[(wid + i * 16) * CDIM + k0 + kk];
#pragma unroll
                        for (int j = 0; j < 8; j++) acc[i][j] += a * bvv[j];
                    }
                }
            }
            __syncthreads();
        }
#pragma unroll
        for (int i = 0; i < 4; i++) {
            if (i < 3 || wid == 0) {
                int r = wid + i * 16;
#pragma unroll
                for (int j = 0; j < 8; j++) {
                    int c = lane + j * 32;
                    out[base + r * CDIM + c] = acc[i][j] + ob[c];
                }
            }
        }
    }
}

// -------------------------- launch ------------------------------------------
extern "C" void kernel_launch(void* const* d_in, const int* in_sizes, int n_in,
                              void* d_out, int out_size) {
    const float* query = (const float*)d_in[0];
    const float* key_  = (const float*)d_in[1];
    const float* value = (const float*)d_in[2];
    const float* mask  = (const float*)d_in[3];
    const float* q_w   = (const float*)d_in[4];
    const float* q_b   = (const float*)d_in[5];
    const float* k_w   = (const float*)d_in[6];
    const float* k_b   = (const float*)d_in[7];
    const float* v_w   = (const float*)d_in[8];
    const float* v_b   = (const float*)d_in[9];
    const float* o_w   = (const float*)d_in[10];
    const float* o_b   = (const float*)d_in[11];
    const float* rpb   = (const float*)d_in[12];
    const int*   ridx  = (const int*)d_in[13];
    float* out = (float*)d_out;

    const int B  = in_sizes[0] / (NTOK * CDIM);   // 4096
    const int nW = in_sizes[3] / (NTOK * NTOK);   // 64

    prep_weights<<<(CDIM * CDIM + 255) / 256, 256>>>(q_w, k_w, v_w, o_w);
    prep_bias<<<(HDS * NTOK * NTOK + 255) / 256, 256>>>(rpb, ridx);

    cudaFuncSetAttribute(window_attn_kernel,
                         cudaFuncAttributeMaxDynamicSharedMemorySize, SMEM_BYTES);
    window_attn_kernel<<<B, NTHREADS, SMEM_BYTES>>>(
        query, key_, value, mask, q_b, k_b, v_b, o_b, out, nW);
}

// round 6
// speedup vs baseline: 1.1066x; 1.1066x over previous
#include <cuda_runtime.h>

// ---------------------------------------------------------------------------
// WindowMCA fused kernel, round 5: GEMM inner loops converted to packed
// fma.rn.f32x2 (2 FMAs/lane/instr — sm_103a FFMA2 path ptxas never emits),
// warp-parallel softmax. Structure otherwise identical to the passing R4
// kernel (one CTA per window, everything in smem).
// ---------------------------------------------------------------------------

#define NTOK     49
#define CDIM     256
#define HDS      8
#define HDIM     32
#define NTHREADS 512
#define KT       16          // k-tile for weight staging
#define LDN      51          // leading dim of smem q/k/v [C][LDN] (odd -> conflict-free)
#define LDSC     53          // leading dim of smem scores [N][LDSC]
#define SCALE    0.17677669529663687f   // 32^-0.5

// smem layout (floats):
//   sIn : [0, 12544)            staging X, later attention output [n][256]
//   sQ  : [12544, 25600)        [c][LDN]
//   sK  : [25600, 38656)
//   sV  : [38656, 51712)
//   sW  : [51712, 55808)        weight k-tile [KT][256]; reused as scores sS
#define SMEM_FLOATS 55808
#define SMEM_BYTES  (SMEM_FLOATS * 4)

// -------------------------- f32x2 packed helpers ---------------------------
typedef unsigned long long u64;

__device__ __forceinline__ u64 dup2(float v) {
    u64 r;
    asm("mov.b64 %0, {%1, %1};" : "=l"(r) : "f"(v));
    return r;
}
__device__ __forceinline__ void fma2(u64& d, u64 a, u64 b) {
    asm("fma.rn.f32x2 %0, %1, %2, %0;" : "+l"(d) : "l"(a), "l"(b));
}
__device__ __forceinline__ float2 unpack2(u64 v) {
    float2 f;
    asm("mov.b64 {%0, %1}, %2;" : "=f"(f.x), "=f"(f.y) : "l"(v));
    return f;
}

// -------------------------- scratch (device globals) -----------------------
__device__ float g_wqT[CDIM * CDIM];   // W^T with SCALE folded in
__device__ float g_wkT[CDIM * CDIM];
__device__ float g_wvT[CDIM * CDIM];
__device__ float g_woT[CDIM * CDIM];
__device__ float g_bias[HDS * NTOK * NTOK];  // dense rel-pos bias [h][n][m]

// -------------------------- prep kernels -----------------------------------
__global__ void prep_weights(const float* __restrict__ qw, const float* __restrict__ kw,
                             const float* __restrict__ vw, const float* __restrict__ ow) {
    int idx = blockIdx.x * blockDim.x + threadIdx.x;
    if (idx >= CDIM * CDIM) return;
    int o = idx >> 8;          // output channel (row of W)
    int c = idx & 255;         // input channel (contiguous -> coalesced read)
    g_wqT[c * CDIM + o] = qw[idx] * SCALE;   // fold softmax scale into Wq
    g_wkT[c * CDIM + o] = kw[idx];
    g_wvT[c * CDIM + o] = vw[idx];
    g_woT[c * CDIM + o] = ow[idx];
}

__global__ void prep_bias(const float* __restrict__ rpb, const int* __restrict__ relidx) {
    int idx = blockIdx.x * blockDim.x + threadIdx.x;
    if (idx >= HDS * NTOK * NTOK) return;
    int h = idx / (NTOK * NTOK);
    int r = idx % (NTOK * NTOK);
    g_bias[idx] = rpb[relidx[r] * HDS + h];
}

// -------------------------- projection helper ------------------------------
// Computes dst[c][n] = sum_k sIn[n][k] * Wt[k][c] + bias[c]*bscale
// Thread layout: wid -> rows n = wid + i*16 (i<4, guarded),
//                lane -> packed column pairs c = lane*2 + j*64 (j<4).
__device__ __forceinline__ void project_to_smem(
    const float* __restrict__ Wt, const float* __restrict__ bias, float bscale,
    const float* __restrict__ sIn, float* __restrict__ sW, float* __restrict__ dst,
    int tid, int lane, int wid)
{
    u64 acc[4][4];
#pragma unroll
    for (int i = 0; i < 4; i++)
#pragma unroll
        for (int j = 0; j < 4; j++) acc[i][j] = 0ull;   // bit pattern of (0.f, 0.f)

    const float4* W4 = (const float4*)Wt;
    float4* sW4 = (float4*)sW;

    for (int k0 = 0; k0 < CDIM; k0 += KT) {
        // stage W tile [KT][256]
#pragma unroll
        for (int t = 0; t < (KT * CDIM / 4) / NTHREADS; t++)
            sW4[tid + t * NTHREADS] = W4[k0 * (CDIM / 4) + tid + t * NTHREADS];
        __syncthreads();
#pragma unroll
        for (int kk = 0; kk < KT; kk++) {
            u64 w2[4];
#pragma unroll
            for (int j = 0; j < 4; j++)    // LDS.64, conflict-free (lane*2 words)
                w2[j] = *(const u64*)&sW[kk * CDIM + lane * 2 + j * 64];
#pragma unroll
            for (int i = 0; i < 4; i++) {
                if (i < 3 || wid == 0) {   // row r = wid + i*16 < 49
                    u64 a2 = dup2(sIn[(wid + i * 16) * CDIM + k0 + kk]);
#pragma unroll
                    for (int j = 0; j < 4; j++) fma2(acc[i][j], a2, w2[j]);
                }
            }
        }
        __syncthreads();
    }

#pragma unroll
    for (int i = 0; i < 4; i++) {
        if (i < 3 || wid == 0) {
            int r = wid + i * 16;
#pragma unroll
            for (int j = 0; j < 4; j++) {
                int c = lane * 2 + j * 64;
                float2 v = unpack2(acc[i][j]);
                dst[c * LDN + r]       = v.x + bias[c] * bscale;
                dst[(c + 1) * LDN + r] = v.y + bias[c + 1] * bscale;
            }
        }
    }
    __syncthreads();
}

// -------------------------- main fused kernel ------------------------------
__global__ void __launch_bounds__(NTHREADS, 1)
window_attn_kernel(const float* __restrict__ query, const float* __restrict__ key,
                   const float* __restrict__ value, const float* __restrict__ mask,
                   const float* __restrict__ qb, const float* __restrict__ kb,
                   const float* __restrict__ vb, const float* __restrict__ ob,
                   float* __restrict__ out, int nW)
{
    extern __shared__ float smem[];
    float* sIn = smem;
    float* sQ  = smem + 12544;
    float* sK  = smem + 25600;
    float* sV  = smem + 38656;
    float* sW  = smem + 51712;
    float* sS  = sW;                     // reuse weight tile as score buffer

    const int tid  = threadIdx.x;
    const int lane = tid & 31;
    const int wid  = tid >> 5;
    const int b    = blockIdx.x;
    const long base = (long)b * (NTOK * CDIM);

    float4* sIn4 = (float4*)sIn;

    // ---- Q projection ----
    {
        const float4* X4 = (const float4*)(query + base);
        for (int i = tid; i < NTOK * CDIM / 4; i += NTHREADS) sIn4[i] = X4[i];
        __syncthreads();
        project_to_smem(g_wqT, qb, SCALE, sIn, sW, sQ, tid, lane, wid);
    }
    // ---- K projection ----
    {
        const float4* X4 = (const float4*)(key + base);
        for (int i = tid; i < NTOK * CDIM / 4; i += NTHREADS) sIn4[i] = X4[i];
        __syncthreads();
        project_to_smem(g_wkT, kb, 1.f, sIn, sW, sK, tid, lane, wid);
    }
    // ---- V projection ----
    {
        const float4* X4 = (const float4*)(value + base);
        for (int i = tid; i < NTOK * CDIM / 4; i += NTHREADS) sIn4[i] = X4[i];
        __syncthreads();
        project_to_smem(g_wvT, vb, 1.f, sIn, sW, sV, tid, lane, wid);
    }
    // sIn is now free; reused below as attention output [n][256].

    const int w = b % nW;
    const float* maskW = mask + (long)w * NTOK * NTOK;
    const int m0 = lane;
    const int m1 = lane + 32;
    const bool has_m1 = (m1 < NTOK);

    for (int h = 0; h < HDS; h++) {
        const int cb = h * HDIM;

        // ---- scores S[n][m] = sum_d q[n][cb+d] * k[m][cb+d] ----
        float sacc[4][2];
#pragma unroll
        for (int i = 0; i < 4; i++) { sacc[i][0] = 0.f; sacc[i][1] = 0.f; }
#pragma unroll
        for (int d = 0; d < HDIM; d++) {
            const float* kq = sK + (cb + d) * LDN;
            const float* qq = sQ + (cb + d) * LDN;
            float k0v = kq[m0];
            float k1v = has_m1 ? kq[m1] : 0.f;
#pragma unroll
            for (int i = 0; i < 4; i++) {
                if (i < 3 || wid == 0) {
                    float a = qq[wid + i * 16];
                    sacc[i][0] += a * k0v;
                    sacc[i][1] += a * k1v;
                }
            }
        }
        const float* biasH = g_bias + h * NTOK * NTOK;
#pragma unroll
        for (int i = 0; i < 4; i++) {
            if (i < 3 || wid == 0) {
                int n = wid + i * 16;
                sS[n * LDSC + m0] = sacc[i][0] + biasH[n * NTOK + m0] + maskW[n * NTOK + m0];
                if (has_m1)
                    sS[n * LDSC + m1] = sacc[i][1] + biasH[n * NTOK + m1] + maskW[n * NTOK + m1];
            }
        }
        __syncthreads();

        // ---- softmax: one warp per row, shuffle reductions ----
        for (int rr = wid; rr < NTOK; rr += 16) {
            float* row = sS + rr * LDSC;
            float v0 = row[lane];
            float v1 = has_m1 ? row[m1] : -1e30f;
            float mx = fmaxf(v0, v1);
#pragma unroll
            for (int o = 16; o; o >>= 1) mx = fmaxf(mx, __shfl_xor_sync(0xffffffffu, mx, o));
            float e0 = __expf(v0 - mx);
            float e1 = has_m1 ? __expf(v1 - mx) : 0.f;
            float s = e0 + e1;
#pragma unroll
            for (int o = 16; o; o >>= 1) s += __shfl_xor_sync(0xffffffffu, s, o);
            float inv = 1.f / s;
            row[lane] = e0 * inv;
            if (has_m1) row[m1] = e1 * inv;
        }
        __syncthreads();

        // ---- O[n][d] = sum_m P[n][m] * v[m][cb+d]  (d = lane) ----
        float oacc[4] = {0.f, 0.f, 0.f, 0.f};
        const float* vcol = sV + (cb + lane) * LDN;
        for (int m = 0; m < NTOK; m++) {
            float vv = vcol[m];
#pragma unroll
            for (int i = 0; i < 4; i++) {
                if (i < 3 || wid == 0)
                    oacc[i] += sS[(wid + i * 16) * LDSC + m] * vv;
            }
        }
#pragma unroll
        for (int i = 0; i < 4; i++) {
            if (i < 3 || wid == 0)
                sIn[(wid + i * 16) * CDIM + cb + lane] = oacc[i];
        }
        __syncthreads();
    }

    // ---- output projection: out[n][c] = sum_k sIn[n][k] * Wo^T[k][c] + ob[c]
    {
        u64 acc[4][4];
#pragma unroll
        for (int i = 0; i < 4; i++)
#pragma unroll
            for (int j = 0; j < 4; j++) acc[i][j] = 0ull;

        const float4* W4 = (const float4*)g_woT;
        float4* sW4 = (float4*)sW;
        for (int k0 = 0; k0 < CDIM; k0 += KT) {
#pragma unroll
            for (int t = 0; t < (KT * CDIM / 4) / NTHREADS; t++)
                sW4[tid + t * NTHREADS] = W4[k0 * (CDIM / 4) + tid + t * NTHREADS];
            __syncthreads();
#pragma unroll
            for (int kk = 0; kk < KT; kk++) {
                u64 w2[4];
#pragma unroll
                for (int j = 0; j < 4; j++)
                    w2[j] = *(const u64*)&sW[kk * CDIM + lane * 2 + j * 64];
#pragma unroll
                for (int i = 0; i < 4; i++) {
                    if (i < 3 || wid == 0) {
                        u64 a2 = dup2(sIn[(wid + i * 16) * CDIM + k0 + kk]);
#pragma unroll
                        for (int j = 0; j < 4; j++) fma2(acc[i][j], a2, w2[j]);
                    }
                }
            }
            __syncthreads();
        }
#pragma unroll
        for (int i = 0; i < 4; i++) {
            if (i < 3 || wid == 0) {
                int r = wid + i * 16;
#pragma unroll
                for (int j = 0; j < 4; j++) {
                    int c = lane * 2 + j * 64;
                    float2 v = unpack2(acc[i][j]);
                    float2 res;
                    res.x = v.x + ob[c];
                    res.y = v.y + ob[c + 1];
                    *(float2*)&out[base + r * CDIM + c] = res;   // coalesced 64-bit stores
                }
            }
        }
    }
}

// -------------------------- launch ------------------------------------------
extern "C" void kernel_launch(void* const* d_in, const int* in_sizes, int n_in,
                              void* d_out, int out_size) {
    const float* query = (const float*)d_in[0];
    const float* key_  = (const float*)d_in[1];
    const float* value = (const float*)d_in[2];
    const float* mask  = (const float*)d_in[3];
    const float* q_w   = (const float*)d_in[4];
    const float* q_b   = (const float*)d_in[5];
    const float* k_w   = (const float*)d_in[6];
    const float* k_b   = (const float*)d_in[7];
    const float* v_w   = (const float*)d_in[8];
    const float* v_b   = (const float*)d_in[9];
    const float* o_w   = (const float*)d_in[10];
    const float* o_b   = (const float*)d_in[11];
    const float* rpb   = (const float*)d_in[12];
    const int*   ridx  = (const int*)d_in[13];
    float* out = (float*)d_out;

    const int B  = in_sizes[0] / (NTOK * CDIM);   // 4096
    const int nW = in_sizes[3] / (NTOK * NTOK);   // 64

    prep_weights<<<(CDIM * CDIM + 255) / 256, 256>>>(q_w, k_w, v_w, o_w);
    prep_bias<<<(HDS * NTOK * NTOK + 255) / 256, 256>>>(rpb, ridx);

    cudaFuncSetAttribute(window_attn_kernel,
                         cudaFuncAttributeMaxDynamicSharedMemorySize, SMEM_BYTES);
    window_attn_kernel<<<B, NTHREADS, SMEM_BYTES>>>(
        query, key_, value, mask, q_b, k_b, v_b, o_b, out, nW);
}